// round 3
// baseline (speedup 1.0000x reference)
#include <cuda_runtime.h>
#include <math.h>
#include <stdint.h>

namespace {
constexpr int kB = 512, kL = 256, kDin = 384, kD = 300;
constexpr int kMemRow = 13 * 8 * 300;            // 31200 floats / batch row of mem
constexpr int kCOff = 0;                          // c at start of d_out
constexpr int kMemOff = kB * kDin;                // 196608
constexpr int kLogitOff = kMemOff + kB * kMemRow; // 16171008
constexpr int KS = 180;                           // Wr0^T k-rows cached in smem
constexpr int RECUR_SMEM = (kD * KS + 4 * kD) * 4;
constexpr int OUTG_SMEM = 8 * 3900 * 4;
}

__device__ float g_U[(size_t)kL * kB * kD];  // [t][b][j]
__device__ float g_A[kDin * kD];             // in_W @ Wh0
__device__ float g_c0[kD];                   // in_b @ Wh0 + lb0
__device__ float g_WrT[kD * kD];             // Wr0^T: [j][k]
__device__ float g_x0[kB * kD];
__device__ float g_skip[kB * kDin];
__device__ float g_cpre[kB * kDin];

__global__ void prep_kernel(const float* __restrict__ in_W, const float* __restrict__ in_b,
                            const float* __restrict__ Wh, const float* __restrict__ Wr,
                            const float* __restrict__ lb) {
    int idx = blockIdx.x * blockDim.x + threadIdx.x;
    if (idx < kDin * kD) {
        int d = idx / kD, j = idx % kD;
        const float* iw = in_W + (size_t)d * kD;
        float s = 0.f;
        for (int k = 0; k < kD; k++) s += iw[k] * Wh[k * kD + j];
        g_A[idx] = s;
    } else if (idx < kDin * kD + kD * kD) {
        int t = idx - kDin * kD;
        int j = t / kD, k = t % kD;
        g_WrT[t] = Wr[k * kD + j];
    } else if (idx < kDin * kD + kD * kD + kD) {
        int j = idx - kDin * kD - kD * kD;
        float s = lb[j];
        for (int k = 0; k < kD; k++) s += in_b[k] * Wh[k * kD + j];
        g_c0[j] = s;
    }
}

// U = WE @ g_A + g_c0 ;  M=131072 (row = b*256+l), K=384, N=300; out row = l*512+b
__global__ void gemm_u_kernel(const float* __restrict__ we) {
    __shared__ float As[16][64];
    __shared__ float Bs[16][64];
    int tid = threadIdx.x;
    int row0 = blockIdx.y * 64, col0 = blockIdx.x * 64;
    int tm = (tid >> 4) * 4, tn = (tid & 15) * 4;
    float acc[4][4];
#pragma unroll
    for (int i = 0; i < 4; i++)
#pragma unroll
        for (int j = 0; j < 4; j++) acc[i][j] = 0.f;

    for (int k0 = 0; k0 < kDin; k0 += 16) {
        {
            int m = tid >> 2, kk = (tid & 3) * 4;
            float4 v = *(const float4*)&we[(size_t)(row0 + m) * kDin + k0 + kk];
            As[kk + 0][m] = v.x; As[kk + 1][m] = v.y;
            As[kk + 2][m] = v.z; As[kk + 3][m] = v.w;
        }
        {
            int kk = tid >> 4, nn = (tid & 15) * 4, col = col0 + nn;
            float4 v = make_float4(0.f, 0.f, 0.f, 0.f);
            if (col + 3 < kD) v = *(const float4*)&g_A[(size_t)(k0 + kk) * kD + col];
            else {
                if (col     < kD) v.x = g_A[(k0 + kk) * kD + col];
                if (col + 1 < kD) v.y = g_A[(k0 + kk) * kD + col + 1];
                if (col + 2 < kD) v.z = g_A[(k0 + kk) * kD + col + 2];
            }
            *(float4*)&Bs[kk][nn] = v;
        }
        __syncthreads();
#pragma unroll
        for (int k = 0; k < 16; k++) {
            float4 av = *(const float4*)&As[k][tm];
            float4 bv = *(const float4*)&Bs[k][tn];
            acc[0][0] += av.x*bv.x; acc[0][1] += av.x*bv.y; acc[0][2] += av.x*bv.z; acc[0][3] += av.x*bv.w;
            acc[1][0] += av.y*bv.x; acc[1][1] += av.y*bv.y; acc[1][2] += av.y*bv.z; acc[1][3] += av.y*bv.w;
            acc[2][0] += av.z*bv.x; acc[2][1] += av.z*bv.y; acc[2][2] += av.z*bv.z; acc[2][3] += av.z*bv.w;
            acc[3][0] += av.w*bv.x; acc[3][1] += av.w*bv.y; acc[3][2] += av.w*bv.z; acc[3][3] += av.w*bv.w;
        }
        __syncthreads();
    }
#pragma unroll
    for (int ii = 0; ii < 4; ii++) {
        int rin = row0 + tm + ii;
        int orow = ((rin & 255) << 9) + (rin >> 8);
        float* op = g_U + (size_t)orow * kD;
#pragma unroll
        for (int jj = 0; jj < 4; jj++) {
            int col = col0 + tn + jj;
            if (col < kD) op[col] = acc[ii][jj] + g_c0[col];
        }
    }
}

// 128 CTAs x 4 batch rows; 256 sequential steps, no grid sync.
__global__ void recur_kernel(float* __restrict__ mem) {
    extern __shared__ float sm[];
    float* Ws = sm;             // [j][KS]
    float* rs = sm + kD * KS;   // [4][kD]
    int tid = threadIdx.x;
    int b0 = blockIdx.x * 4;

    for (int idx = tid; idx < kD * KS; idx += blockDim.x) {
        int j = idx / KS, k = idx % KS;
        Ws[idx] = g_WrT[j * kD + k];
    }
    for (int idx = tid; idx < 4 * kD; idx += blockDim.x) rs[idx] = 0.f;
    __syncthreads();

    const int j = tid;
    const bool act = (j < kD);
    float* m0 = mem + (size_t)b0 * kMemRow;
    const float inv13 = 1.f / 13.f;

    for (int t = 0; t < kL; t++) {
        int ptr = t % 13;
        float d0 = 0.f, d1 = 0.f, d2 = 0.f, d3 = 0.f;
        if (act) {
            float a0 = 0.f, a1 = 0.f, a2 = 0.f, a3 = 0.f;
            const float4* wp = (const float4*)(Ws + j * KS);
            const float4* gp = (const float4*)(g_WrT + (size_t)j * kD);
            const float4* r0 = (const float4*)(rs);
            const float4* r1 = (const float4*)(rs + kD);
            const float4* r2 = (const float4*)(rs + 2 * kD);
            const float4* r3 = (const float4*)(rs + 3 * kD);
#pragma unroll 5
            for (int kk = 0; kk < KS / 4; kk++) {
                float4 w = wp[kk];
                float4 q0 = r0[kk], q1 = r1[kk], q2 = r2[kk], q3 = r3[kk];
                a0 += q0.x*w.x + q0.y*w.y + q0.z*w.z + q0.w*w.w;
                a1 += q1.x*w.x + q1.y*w.y + q1.z*w.z + q1.w*w.w;
                a2 += q2.x*w.x + q2.y*w.y + q2.z*w.z + q2.w*w.w;
                a3 += q3.x*w.x + q3.y*w.y + q3.z*w.z + q3.w*w.w;
            }
#pragma unroll 5
            for (int kk = KS / 4; kk < kD / 4; kk++) {
                float4 w = gp[kk];
                float4 q0 = r0[kk], q1 = r1[kk], q2 = r2[kk], q3 = r3[kk];
                a0 += q0.x*w.x + q0.y*w.y + q0.z*w.z + q0.w*w.w;
                a1 += q1.x*w.x + q1.y*w.y + q1.z*w.z + q1.w*w.w;
                a2 += q2.x*w.x + q2.y*w.y + q2.z*w.z + q2.w*w.w;
                a3 += q3.x*w.x + q3.y*w.y + q3.z*w.z + q3.w*w.w;
            }
            const float* up = g_U + ((size_t)t * kB + b0) * kD + j;
            float h0 = tanhf(up[0]        + a0 * inv13);
            float h1 = tanhf(up[kD]       + a1 * inv13);
            float h2 = tanhf(up[2 * kD]   + a2 * inv13);
            float h3 = tanhf(up[3 * kD]   + a3 * inv13);
            float* ms = m0 + ptr * 2400 + j;
            float o0 = ms[0];           ms[0]           = h0; d0 = h0 - o0;
            float o1 = ms[kMemRow];     ms[kMemRow]     = h1; d1 = h1 - o1;
            float o2 = ms[2*kMemRow];   ms[2*kMemRow]   = h2; d2 = h2 - o2;
            float o3 = ms[3*kMemRow];   ms[3*kMemRow]   = h3; d3 = h3 - o3;
        }
        __syncthreads();
        if (act) {
            rs[j]        += d0;
            rs[kD + j]   += d1;
            rs[2*kD + j] += d2;
            rs[3*kD + j] += d3;
        }
        __syncthreads();
    }
}

__global__ void x0_kernel(const float* __restrict__ we, const float* __restrict__ in_W,
                          const float* __restrict__ in_b) {
    int idx = blockIdx.x * blockDim.x + threadIdx.x;
    if (idx >= kB * kD) return;
    int b = idx / kD, j = idx % kD;
    const float* wr = we + (size_t)b * kL * kDin;
    float s = in_b[j];
    for (int d = 0; d < kDin; d++) s += wr[d] * in_W[d * kD + j];
    g_x0[idx] = s;
}

__global__ void skip_kernel(const float* __restrict__ skip_W, const float* __restrict__ skip_b) {
    int idx = blockIdx.x * blockDim.x + threadIdx.x;
    if (idx >= kB * kDin) return;
    int b = idx / kDin, i = idx % kDin;
    const float* x = g_x0 + (size_t)b * kD;
    float s = skip_b[i];
    for (int jj = 0; jj < kD; jj++) s += x[jj] * skip_W[jj * kDin + i];
    g_skip[idx] = s;
}

// cpre = mem_layer0 @ out_W(layer0 rows). 64 CTAs x 8 rows, 384 threads.
__global__ void outgemm_kernel(const float* __restrict__ mem, const float* __restrict__ outW) {
    extern __shared__ float X[];  // [8][3900]
    int b0 = blockIdx.x * 8, tid = threadIdx.x;
    for (int idx = tid; idx < 8 * 3900; idx += 384) {
        int r = idx / 3900, k = idx % 3900;
        int s = k / 300, d = k % 300;
        X[idx] = mem[(size_t)(b0 + r) * kMemRow + s * 2400 + d];
    }
    __syncthreads();
    int i = tid;
    float acc[8];
#pragma unroll
    for (int r = 0; r < 8; r++) acc[r] = 0.f;
    for (int s = 0; s < 13; s++) {
        const float* wb = outW + (size_t)s * 2400 * kDin + i;
        const float* Xs = X + s * 300;
        for (int d4 = 0; d4 < 75; d4++) {
            float w0 = wb[(size_t)(d4 * 4 + 0) * kDin];
            float w1 = wb[(size_t)(d4 * 4 + 1) * kDin];
            float w2 = wb[(size_t)(d4 * 4 + 2) * kDin];
            float w3 = wb[(size_t)(d4 * 4 + 3) * kDin];
#pragma unroll
            for (int r = 0; r < 8; r++) {
                float4 q = *(const float4*)&Xs[r * 3900 + d4 * 4];
                acc[r] += q.x * w0 + q.y * w1 + q.z * w2 + q.w * w3;
            }
        }
    }
#pragma unroll
    for (int r = 0; r < 8; r++) g_cpre[(size_t)(b0 + r) * kDin + i] = acc[r];
}

// layernorm(cpre + out_b + skip) -> c; logit = relu(c@W1+b1)@W2+b2
__global__ void final_kernel(const float* __restrict__ out_b,
                             const float* __restrict__ ln_g, const float* __restrict__ ln_b,
                             const float* __restrict__ W1, const float* __restrict__ b1,
                             const float* __restrict__ W2, const float* __restrict__ b2,
                             float* __restrict__ out) {
    __shared__ float cv[kDin];
    __shared__ float red[16];
    __shared__ float hid[64];
    int b = blockIdx.x, tid = threadIdx.x;
    int lane = tid & 31, wid = tid >> 5;  // 12 warps

    float v = g_cpre[(size_t)b * kDin + tid] + out_b[tid] + g_skip[(size_t)b * kDin + tid];

    float s = v;
#pragma unroll
    for (int o = 16; o > 0; o >>= 1) s += __shfl_xor_sync(0xffffffffu, s, o);
    if (lane == 0) red[wid] = s;
    __syncthreads();
    if (tid == 0) {
        float t = 0.f;
        for (int w = 0; w < 12; w++) t += red[w];
        red[12] = t / kDin;
    }
    __syncthreads();
    float mu = red[12];
    float dv = v - mu;
    float s2 = dv * dv;
#pragma unroll
    for (int o = 16; o > 0; o >>= 1) s2 += __shfl_xor_sync(0xffffffffu, s2, o);
    if (lane == 0) red[wid] = s2;
    __syncthreads();
    if (tid == 0) {
        float t = 0.f;
        for (int w = 0; w < 12; w++) t += red[w];
        red[13] = rsqrtf(t / kDin + 1e-5f);
    }
    __syncthreads();
    float c = dv * red[13] * ln_g[tid] + ln_b[tid];
    out[(size_t)b * kDin + tid] = c;
    cv[tid] = c;
    __syncthreads();

    if (tid < 64) {
        float a = b1[tid];
        for (int d = 0; d < kDin; d++) a += cv[d] * W1[(size_t)d * 64 + tid];
        hid[tid] = fmaxf(a, 0.f) * W2[tid];
    }
    __syncthreads();
    if (tid == 0) {
        float lg = b2[0];
        for (int h = 0; h < 64; h++) lg += hid[h];
        out[kLogitOff + b] = lg;
    }
}

extern "C" void kernel_launch(void* const* d_in, const int* in_sizes, int n_in,
                              void* d_out, int out_size) {
    const float* we     = (const float*)d_in[0];
    const float* in_W   = (const float*)d_in[1];
    const float* in_b   = (const float*)d_in[2];
    const float* Wh     = (const float*)d_in[3];
    const float* Wr     = (const float*)d_in[4];
    const float* lb     = (const float*)d_in[5];
    const float* skip_W = (const float*)d_in[6];
    const float* skip_b = (const float*)d_in[7];
    const float* out_W  = (const float*)d_in[8];
    const float* out_b  = (const float*)d_in[9];
    const float* ln_g   = (const float*)d_in[10];
    const float* ln_b   = (const float*)d_in[11];
    const float* sh_W1  = (const float*)d_in[12];
    const float* sh_b1  = (const float*)d_in[13];
    const float* sh_W2  = (const float*)d_in[14];
    const float* sh_b2  = (const float*)d_in[15];
    float* out = (float*)d_out;

    cudaFuncSetAttribute(recur_kernel, cudaFuncAttributeMaxDynamicSharedMemorySize, RECUR_SMEM);
    cudaFuncSetAttribute(outgemm_kernel, cudaFuncAttributeMaxDynamicSharedMemorySize, OUTG_SMEM);

    // zero the mem region of the output (layers >=1 stay zero; recurrence fills layer 0)
    cudaMemsetAsync(out + kMemOff, 0, (size_t)kB * kMemRow * sizeof(float));

    {
        int total = kDin * kD + kD * kD + kD;
        prep_kernel<<<(total + 255) / 256, 256>>>(in_W, in_b, Wh, Wr, lb);
    }
    {
        dim3 grid((kD + 63) / 64, (kB * kL) / 64);
        gemm_u_kernel<<<grid, 256>>>(we);
    }
    x0_kernel<<<(kB * kD + 255) / 256, 256>>>(we, in_W, in_b);
    skip_kernel<<<(kB * kDin + 255) / 256, 256>>>(skip_W, skip_b);

    recur_kernel<<<kB / 4, 320, RECUR_SMEM>>>(out + kMemOff);

    outgemm_kernel<<<kB / 8, 384, OUTG_SMEM>>>(out + kMemOff, out_W);

    final_kernel<<<kB, kDin>>>(out_b, ln_g, ln_b, sh_W1, sh_b1, sh_W2, sh_b2, out);
}

// round 4
// speedup vs baseline: 1.6415x; 1.6415x over previous
#include <cuda_runtime.h>
#include <math.h>
#include <stdint.h>

namespace {
constexpr int kB = 512, kL = 256, kDin = 384, kD = 300;
constexpr int kMemRow = 13 * 8 * 300;             // 31200 floats / batch row of mem
constexpr int kMemOff = kB * kDin;                // 196608
constexpr int kLogitOff = kMemOff + kB * kMemRow; // 16171008
constexpr int KS = 180;                           // Wr0^T k-rows cached in smem
constexpr int KT = kD - KS;                       // 120 tail k-rows in registers
constexpr int RECUR_SMEM = (kD * KS + 4 * kD) * 4;
constexpr int OUTG_SMEM = 8 * 3900 * 4;
}

typedef unsigned long long ull;

__device__ __forceinline__ void ffma2(ull& d, ull a, ull b, ull c) {
    asm("fma.rn.f32x2 %0, %1, %2, %3;" : "=l"(d) : "l"(a), "l"(b), "l"(c));
}
__device__ __forceinline__ float pairsum(ull v) {
    float lo = __uint_as_float((unsigned)(v & 0xffffffffu));
    float hi = __uint_as_float((unsigned)(v >> 32));
    return lo + hi;
}

__device__ float g_U[(size_t)kL * kB * kD];  // [t][b][j]
__device__ float g_A[kDin * kD];             // in_W @ Wh0
__device__ float g_c0[kD];                   // in_b @ Wh0 + lb0
__device__ float g_WrT[kD * kD];             // Wr0^T: [j][k]
__device__ float g_x0[kB * kD];
__device__ float g_skip[kB * kDin];
__device__ float g_cpre[kB * kDin];

__global__ void prep_kernel(const float* __restrict__ in_W, const float* __restrict__ in_b,
                            const float* __restrict__ Wh, const float* __restrict__ Wr,
                            const float* __restrict__ lb) {
    int idx = blockIdx.x * blockDim.x + threadIdx.x;
    if (idx < kDin * kD) {
        int d = idx / kD, j = idx % kD;
        const float* iw = in_W + (size_t)d * kD;
        float s = 0.f;
        for (int k = 0; k < kD; k++) s += iw[k] * Wh[k * kD + j];
        g_A[idx] = s;
    } else if (idx < kDin * kD + kD * kD) {
        int t = idx - kDin * kD;
        int j = t / kD, k = t % kD;
        g_WrT[t] = Wr[k * kD + j];
    } else if (idx < kDin * kD + kD * kD + kD) {
        int j = idx - kDin * kD - kD * kD;
        float s = lb[j];
        for (int k = 0; k < kD; k++) s += in_b[k] * Wh[k * kD + j];
        g_c0[j] = s;
    }
}

// ---------------------------------------------------------------------------
// U = WE @ g_A + g_c0 via FFMA2 (k-paired). M=131072 (row=b*256+l), K=384, N=300.
// BM=128, BN=64, BK=16; 256 threads, 8Mx4N per thread. Out row = l*512+b.
// ---------------------------------------------------------------------------
#define ASTRIDE 18
__global__ __launch_bounds__(256) void gemm_u_kernel(const float* __restrict__ we) {
    __shared__ float As[128 * ASTRIDE];  // [m][k], stride 18 (conflict-free 8B banks)
    __shared__ float Bs[64 * ASTRIDE];   // [n][k]
    int tid = threadIdx.x;
    int row0 = blockIdx.y * 128, col0 = blockIdx.x * 64;
    int mg = tid >> 4, ng = tid & 15;    // 16 x 16

    ull acc[8][4];
#pragma unroll
    for (int i = 0; i < 8; i++)
#pragma unroll
        for (int j = 0; j < 4; j++) acc[i][j] = 0ull;

    for (int k0 = 0; k0 < kDin; k0 += 16) {
        // load A tile: 512 float4 total, 2 per thread, stored as scalars (stride 18)
#pragma unroll
        for (int i = 0; i < 2; i++) {
            int fid = tid * 2 + i;
            int m = fid >> 2, kq = (fid & 3) * 4;
            float4 v = *(const float4*)&we[(size_t)(row0 + m) * kDin + k0 + kq];
            float* dst = &As[m * ASTRIDE + kq];
            dst[0] = v.x; dst[1] = v.y; dst[2] = v.z; dst[3] = v.w;
        }
        // load B tile: 16k x 64n, 4 per thread (coalesced over n), transposed store
        {
            int n = tid & 63, kb = tid >> 6;  // kb in 0..3
#pragma unroll
            for (int i = 0; i < 4; i++) {
                int k = kb * 4 + i;
                int col = col0 + n;
                float v = (col < kD) ? g_A[(size_t)(k0 + k) * kD + col] : 0.f;
                Bs[n * ASTRIDE + k] = v;
            }
        }
        __syncthreads();
#pragma unroll
        for (int kk = 0; kk < 8; kk++) {
            ull a[8], b[4];
#pragma unroll
            for (int i = 0; i < 8; i++)
                a[i] = *(const ull*)&As[(mg * 8 + i) * ASTRIDE + kk * 2];
#pragma unroll
            for (int j = 0; j < 4; j++)
                b[j] = *(const ull*)&Bs[(ng * 4 + j) * ASTRIDE + kk * 2];
#pragma unroll
            for (int i = 0; i < 8; i++)
#pragma unroll
                for (int j = 0; j < 4; j++) ffma2(acc[i][j], a[i], b[j], acc[i][j]);
        }
        __syncthreads();
    }

    int colb = col0 + ng * 4;
    float c0v[4];
#pragma unroll
    for (int j = 0; j < 4; j++) c0v[j] = (colb + j < kD) ? g_c0[colb + j] : 0.f;
#pragma unroll
    for (int i = 0; i < 8; i++) {
        int rin = row0 + mg * 8 + i;
        int orow = ((rin & 255) << 9) + (rin >> 8);
        float* op = g_U + (size_t)orow * kD;
        float r[4];
#pragma unroll
        for (int j = 0; j < 4; j++) r[j] = pairsum(acc[i][j]) + c0v[j];
        if (colb + 3 < kD) {
            *(float4*)&op[colb] = make_float4(r[0], r[1], r[2], r[3]);
        } else {
#pragma unroll
            for (int j = 0; j < 4; j++)
                if (colb + j < kD) op[colb + j] = r[j];
        }
    }
}

// ---------------------------------------------------------------------------
// Recurrence: 128 CTAs x 4 batch rows, no grid sync. FFMA2 k-paired.
// Wr0^T: k<180 in smem (j-major stride 180; 45 float4 -> conflict-free),
// k>=180 in registers (60 ull pairs per thread).
// ---------------------------------------------------------------------------
__global__ __launch_bounds__(320, 1) void recur_kernel(float* __restrict__ mem) {
    extern __shared__ float sm[];
    float* Ws = sm;             // [j][KS]
    float* rs = sm + kD * KS;   // [row][kD], 4 rows
    int tid = threadIdx.x;
    int b0 = blockIdx.x * 4;

    for (int idx = tid; idx < kD * KS; idx += blockDim.x) {
        int j = idx / KS, k = idx % KS;
        Ws[idx] = g_WrT[j * kD + k];
    }
    for (int idx = tid; idx < 4 * kD; idx += blockDim.x) rs[idx] = 0.f;

    const int j = tid;
    const bool act = (j < kD);

    // tail of Wr0^T row j in registers as 60 k-pairs
    ull wr[KT / 2];
    if (act) {
#pragma unroll
        for (int i = 0; i < KT / 2; i++)
            wr[i] = *(const ull*)&g_WrT[(size_t)j * kD + KS + 2 * i];
    }
    __syncthreads();

    float* m0 = mem + (size_t)b0 * kMemRow;
    const float inv13 = 1.f / 13.f;

    for (int t = 0; t < kL; t++) {
        int ptr = t % 13;
        float d0 = 0.f, d1 = 0.f, d2 = 0.f, d3 = 0.f;
        if (act) {
            // prefetch U and old slot values
            const float* up = g_U + ((size_t)t * kB + b0) * kD + j;
            float u0 = up[0], u1 = up[kD], u2 = up[2 * kD], u3 = up[3 * kD];
            float* ms = m0 + ptr * 2400 + j;
            float o0 = ms[0], o1 = ms[kMemRow], o2 = ms[2 * kMemRow], o3 = ms[3 * kMemRow];

            ull acc0 = 0, acc1 = 0, acc2 = 0, acc3 = 0;
            const ull* wp = (const ull*)(Ws + j * KS);
            const ull* r0p = (const ull*)(rs);
            const ull* r1p = (const ull*)(rs + kD);
            const ull* r2p = (const ull*)(rs + 2 * kD);
            const ull* r3p = (const ull*)(rs + 3 * kD);
#pragma unroll
            for (int kk = 0; kk < KS / 2; kk++) {
                ull w = wp[kk];
                ffma2(acc0, r0p[kk], w, acc0);
                ffma2(acc1, r1p[kk], w, acc1);
                ffma2(acc2, r2p[kk], w, acc2);
                ffma2(acc3, r3p[kk], w, acc3);
            }
#pragma unroll
            for (int kk = 0; kk < KT / 2; kk++) {
                ull w = wr[kk];
                ffma2(acc0, r0p[KS / 2 + kk], w, acc0);
                ffma2(acc1, r1p[KS / 2 + kk], w, acc1);
                ffma2(acc2, r2p[KS / 2 + kk], w, acc2);
                ffma2(acc3, r3p[KS / 2 + kk], w, acc3);
            }
            float h0 = tanhf(u0 + pairsum(acc0) * inv13);
            float h1 = tanhf(u1 + pairsum(acc1) * inv13);
            float h2 = tanhf(u2 + pairsum(acc2) * inv13);
            float h3 = tanhf(u3 + pairsum(acc3) * inv13);
            ms[0]           = h0; d0 = h0 - o0;
            ms[kMemRow]     = h1; d1 = h1 - o1;
            ms[2 * kMemRow] = h2; d2 = h2 - o2;
            ms[3 * kMemRow] = h3; d3 = h3 - o3;
        }
        __syncthreads();
        if (act) {
            rs[j]          += d0;
            rs[kD + j]     += d1;
            rs[2 * kD + j] += d2;
            rs[3 * kD + j] += d3;
        }
        __syncthreads();
    }
}

__global__ void x0_kernel(const float* __restrict__ we, const float* __restrict__ in_W,
                          const float* __restrict__ in_b) {
    int idx = blockIdx.x * blockDim.x + threadIdx.x;
    if (idx >= kB * kD) return;
    int b = idx / kD, j = idx % kD;
    const float* wr = we + (size_t)b * kL * kDin;
    float s = in_b[j];
    for (int d = 0; d < kDin; d++) s += wr[d] * in_W[d * kD + j];
    g_x0[idx] = s;
}

__global__ void skip_kernel(const float* __restrict__ skip_W, const float* __restrict__ skip_b) {
    int idx = blockIdx.x * blockDim.x + threadIdx.x;
    if (idx >= kB * kDin) return;
    int b = idx / kDin, i = idx % kDin;
    const float* x = g_x0 + (size_t)b * kD;
    float s = skip_b[i];
    for (int jj = 0; jj < kD; jj++) s += x[jj] * skip_W[jj * kDin + i];
    g_skip[idx] = s;
}

// cpre = mem_layer0 @ out_W(layer0 rows). 64 CTAs x 8 rows, 384 threads.
__global__ void outgemm_kernel(const float* __restrict__ mem, const float* __restrict__ outW) {
    extern __shared__ float X[];  // [8][3900]
    int b0 = blockIdx.x * 8, tid = threadIdx.x;
    for (int idx = tid; idx < 8 * 3900; idx += 384) {
        int r = idx / 3900, k = idx % 3900;
        int s = k / 300, d = k % 300;
        X[idx] = mem[(size_t)(b0 + r) * kMemRow + s * 2400 + d];
    }
    __syncthreads();
    int i = tid;
    float acc[8];
#pragma unroll
    for (int r = 0; r < 8; r++) acc[r] = 0.f;
    for (int s = 0; s < 13; s++) {
        const float* wb = outW + (size_t)s * 2400 * kDin + i;
        const float* Xs = X + s * 300;
        for (int d4 = 0; d4 < 75; d4++) {
            float w0 = wb[(size_t)(d4 * 4 + 0) * kDin];
            float w1 = wb[(size_t)(d4 * 4 + 1) * kDin];
            float w2 = wb[(size_t)(d4 * 4 + 2) * kDin];
            float w3 = wb[(size_t)(d4 * 4 + 3) * kDin];
#pragma unroll
            for (int r = 0; r < 8; r++) {
                float4 q = *(const float4*)&Xs[r * 3900 + d4 * 4];
                acc[r] += q.x * w0 + q.y * w1 + q.z * w2 + q.w * w3;
            }
        }
    }
#pragma unroll
    for (int r = 0; r < 8; r++) g_cpre[(size_t)(b0 + r) * kDin + i] = acc[r];
}

__global__ void final_kernel(const float* __restrict__ out_b,
                             const float* __restrict__ ln_g, const float* __restrict__ ln_b,
                             const float* __restrict__ W1, const float* __restrict__ b1,
                             const float* __restrict__ W2, const float* __restrict__ b2,
                             float* __restrict__ out) {
    __shared__ float cv[kDin];
    __shared__ float red[16];
    __shared__ float hid[64];
    int b = blockIdx.x, tid = threadIdx.x;
    int lane = tid & 31, wid = tid >> 5;

    float v = g_cpre[(size_t)b * kDin + tid] + out_b[tid] + g_skip[(size_t)b * kDin + tid];

    float s = v;
#pragma unroll
    for (int o = 16; o > 0; o >>= 1) s += __shfl_xor_sync(0xffffffffu, s, o);
    if (lane == 0) red[wid] = s;
    __syncthreads();
    if (tid == 0) {
        float t = 0.f;
        for (int w = 0; w < 12; w++) t += red[w];
        red[12] = t / kDin;
    }
    __syncthreads();
    float mu = red[12];
    float dv = v - mu;
    float s2 = dv * dv;
#pragma unroll
    for (int o = 16; o > 0; o >>= 1) s2 += __shfl_xor_sync(0xffffffffu, s2, o);
    if (lane == 0) red[wid] = s2;
    __syncthreads();
    if (tid == 0) {
        float t = 0.f;
        for (int w = 0; w < 12; w++) t += red[w];
        red[13] = rsqrtf(t / kDin + 1e-5f);
    }
    __syncthreads();
    float c = dv * red[13] * ln_g[tid] + ln_b[tid];
    out[(size_t)b * kDin + tid] = c;
    cv[tid] = c;
    __syncthreads();

    if (tid < 64) {
        float a = b1[tid];
        for (int d = 0; d < kDin; d++) a += cv[d] * W1[(size_t)d * 64 + tid];
        hid[tid] = fmaxf(a, 0.f) * W2[tid];
    }
    __syncthreads();
    if (tid == 0) {
        float lg = b2[0];
        for (int h = 0; h < 64; h++) lg += hid[h];
        out[kLogitOff + b] = lg;
    }
}

extern "C" void kernel_launch(void* const* d_in, const int* in_sizes, int n_in,
                              void* d_out, int out_size) {
    const float* we     = (const float*)d_in[0];
    const float* in_W   = (const float*)d_in[1];
    const float* in_b   = (const float*)d_in[2];
    const float* Wh     = (const float*)d_in[3];
    const float* Wr     = (const float*)d_in[4];
    const float* lb     = (const float*)d_in[5];
    const float* skip_W = (const float*)d_in[6];
    const float* skip_b = (const float*)d_in[7];
    const float* out_W  = (const float*)d_in[8];
    const float* out_b  = (const float*)d_in[9];
    const float* ln_g   = (const float*)d_in[10];
    const float* ln_b   = (const float*)d_in[11];
    const float* sh_W1  = (const float*)d_in[12];
    const float* sh_b1  = (const float*)d_in[13];
    const float* sh_W2  = (const float*)d_in[14];
    const float* sh_b2  = (const float*)d_in[15];
    float* out = (float*)d_out;

    cudaFuncSetAttribute(recur_kernel, cudaFuncAttributeMaxDynamicSharedMemorySize, RECUR_SMEM);
    cudaFuncSetAttribute(outgemm_kernel, cudaFuncAttributeMaxDynamicSharedMemorySize, OUTG_SMEM);

    cudaMemsetAsync(out + kMemOff, 0, (size_t)kB * kMemRow * sizeof(float));

    {
        int total = kDin * kD + kD * kD + kD;
        prep_kernel<<<(total + 255) / 256, 256>>>(in_W, in_b, Wh, Wr, lb);
    }
    {
        dim3 grid((kD + 63) / 64, (kB * kL) / 128);
        gemm_u_kernel<<<grid, 256>>>(we);
    }
    x0_kernel<<<(kB * kD + 255) / 256, 256>>>(we, in_W, in_b);
    skip_kernel<<<(kB * kDin + 255) / 256, 256>>>(skip_W, skip_b);

    recur_kernel<<<kB / 4, 320, RECUR_SMEM>>>(out + kMemOff);

    outgemm_kernel<<<kB / 8, 384, OUTG_SMEM>>>(out + kMemOff, out_W);

    final_kernel<<<kB, kDin>>>(out_b, ln_g, ln_b, sh_W1, sh_b1, sh_W2, sh_b2, out);
}

// round 5
// speedup vs baseline: 1.8487x; 1.1262x over previous
#include <cuda_runtime.h>
#include <math.h>
#include <stdint.h>

namespace {
constexpr int kB = 512, kL = 256, kDin = 384, kD = 300;
constexpr int kMemRow = 13 * 8 * 300;             // 31200 floats / batch row of mem
constexpr int kMemOff = kB * kDin;                // 196608
constexpr int kLogitOff = kMemOff + kB * kMemRow; // 16171008
constexpr int KS = 180;                           // Wr0^T k-rows cached in smem
constexpr int KT = kD - KS;                       // 120 tail k-rows in registers
constexpr int RECUR_SMEM = (kD * KS + 8 * kD) * 4;   // Ws + 2x rs buffers = 225600 B
constexpr int OUTG_SMEM = 8 * 3900 * 4;
}

typedef unsigned long long ull;

__device__ __forceinline__ void ffma2(ull& d, ull a, ull b, ull c) {
    asm("fma.rn.f32x2 %0, %1, %2, %3;" : "=l"(d) : "l"(a), "l"(b), "l"(c));
}
__device__ __forceinline__ float pairsum(ull v) {
    float lo = __uint_as_float((unsigned)(v & 0xffffffffu));
    float hi = __uint_as_float((unsigned)(v >> 32));
    return lo + hi;
}
__device__ __forceinline__ ull packf2(float lo, float hi) {
    ull r; asm("mov.b64 %0, {%1, %2};" : "=l"(r) : "f"(lo), "f"(hi)); return r;
}

__device__ float g_U[(size_t)kL * kB * kD];  // [t][b][j]
__device__ float g_A[kDin * kD];             // in_W @ Wh0
__device__ float g_c0[kD];                   // in_b @ Wh0 + lb0
__device__ float g_WrT[kD * kD];             // Wr0^T: [j][k]
__device__ float g_x0[kB * kD];
__device__ float g_skip[kB * kDin];
__device__ float g_cpre[kB * kDin];

__global__ void prep_kernel(const float* __restrict__ in_W, const float* __restrict__ in_b,
                            const float* __restrict__ Wh, const float* __restrict__ Wr,
                            const float* __restrict__ lb) {
    int idx = blockIdx.x * blockDim.x + threadIdx.x;
    if (idx < kDin * kD) {
        int d = idx / kD, j = idx % kD;
        const float* iw = in_W + (size_t)d * kD;
        float s = 0.f;
        for (int k = 0; k < kD; k++) s += iw[k] * Wh[k * kD + j];
        g_A[idx] = s;
    } else if (idx < kDin * kD + kD * kD) {
        int t = idx - kDin * kD;
        int j = t / kD, k = t % kD;
        g_WrT[t] = Wr[k * kD + j];
    } else if (idx < kDin * kD + kD * kD + kD) {
        int j = idx - kDin * kD - kD * kD;
        float s = lb[j];
        for (int k = 0; k < kD; k++) s += in_b[k] * Wh[k * kD + j];
        g_c0[j] = s;
    }
}

// ---------------------------------------------------------------------------
// U = WE @ g_A + g_c0 via FFMA2. BM=128, BN=64, BK=16; 256 thr, 8Mx4N/thread.
// M=131072 (row=b*256+l) -> out row = l*512+b.
// ---------------------------------------------------------------------------
#define ASTRIDE 18
__global__ __launch_bounds__(256) void gemm_u_kernel(const float* __restrict__ we) {
    __shared__ float As[128 * ASTRIDE];
    __shared__ float Bs[64 * ASTRIDE];
    int tid = threadIdx.x;
    int row0 = blockIdx.y * 128, col0 = blockIdx.x * 64;
    int mg = tid >> 4, ng = tid & 15;

    ull acc[8][4];
#pragma unroll
    for (int i = 0; i < 8; i++)
#pragma unroll
        for (int j = 0; j < 4; j++) acc[i][j] = 0ull;

    for (int k0 = 0; k0 < kDin; k0 += 16) {
#pragma unroll
        for (int i = 0; i < 2; i++) {
            int fid = tid * 2 + i;
            int m = fid >> 2, kq = (fid & 3) * 4;
            float4 v = *(const float4*)&we[(size_t)(row0 + m) * kDin + k0 + kq];
            float* dst = &As[m * ASTRIDE + kq];
            dst[0] = v.x; dst[1] = v.y; dst[2] = v.z; dst[3] = v.w;
        }
        {
            int n = tid & 63, kb = tid >> 6;
#pragma unroll
            for (int i = 0; i < 4; i++) {
                int k = kb * 4 + i;
                int col = col0 + n;
                float v = (col < kD) ? g_A[(size_t)(k0 + k) * kD + col] : 0.f;
                Bs[n * ASTRIDE + k] = v;
            }
        }
        __syncthreads();
#pragma unroll
        for (int kk = 0; kk < 8; kk++) {
            ull a[8], b[4];
#pragma unroll
            for (int i = 0; i < 8; i++)
                a[i] = *(const ull*)&As[(mg * 8 + i) * ASTRIDE + kk * 2];
#pragma unroll
            for (int j = 0; j < 4; j++)
                b[j] = *(const ull*)&Bs[(ng * 4 + j) * ASTRIDE + kk * 2];
#pragma unroll
            for (int i = 0; i < 8; i++)
#pragma unroll
                for (int j = 0; j < 4; j++) ffma2(acc[i][j], a[i], b[j], acc[i][j]);
        }
        __syncthreads();
    }

    int colb = col0 + ng * 4;
    float c0v[4];
#pragma unroll
    for (int j = 0; j < 4; j++) c0v[j] = (colb + j < kD) ? g_c0[colb + j] : 0.f;
#pragma unroll
    for (int i = 0; i < 8; i++) {
        int rin = row0 + mg * 8 + i;
        int orow = ((rin & 255) << 9) + (rin >> 8);
        float* op = g_U + (size_t)orow * kD;
        float r[4];
#pragma unroll
        for (int j = 0; j < 4; j++) r[j] = pairsum(acc[i][j]) + c0v[j];
        if (colb + 3 < kD) {
            *(float4*)&op[colb] = make_float4(r[0], r[1], r[2], r[3]);
        } else {
#pragma unroll
            for (int j = 0; j < 4; j++)
                if (colb + j < kD) op[colb + j] = r[j];
        }
    }
}

// ---------------------------------------------------------------------------
// Recurrence: 128 CTAs x 4 batch rows. LDS.128 operands, FFMA2 math,
// single barrier per step via rs double-buffer. Tail W in registers.
// ---------------------------------------------------------------------------
__global__ __launch_bounds__(320, 1) void recur_kernel(float* __restrict__ mem) {
    extern __shared__ float sm[];
    float* Ws  = sm;                 // [j][KS] stride 180 floats (16B aligned rows)
    float* rsA = sm + kD * KS;       // [4][kD]
    float* rsB = rsA + 4 * kD;       // [4][kD]
    int tid = threadIdx.x;
    int b0 = blockIdx.x * 4;

    // vectorized Ws load: row j of g_WrT, first KS entries
    for (int idx = tid; idx < kD * (KS / 4); idx += blockDim.x) {
        int j = idx / (KS / 4), q = idx % (KS / 4);
        *(float4*)&Ws[j * KS + q * 4] = *(const float4*)&g_WrT[(size_t)j * kD + q * 4];
    }
    for (int idx = tid; idx < 4 * kD; idx += blockDim.x) { rsA[idx] = 0.f; rsB[idx] = 0.f; }

    const int j = tid;
    const bool act = (j < kD);

    ulonglong2 wr[KT / 4];  // 30 x 16B = tail k=180..299 of row j
    if (act) {
#pragma unroll
        for (int i = 0; i < KT / 4; i++)
            wr[i] = *(const ulonglong2*)&g_WrT[(size_t)j * kD + KS + 4 * i];
    }
    __syncthreads();

    float* m0 = mem + (size_t)b0 * kMemRow;
    const float inv13 = 1.f / 13.f;
    float* ra = rsA;
    float* rb = rsB;

    for (int t = 0; t < kL; t++) {
        int ptr = t % 13;
        if (act) {
            const float* up = g_U + ((size_t)t * kB + b0) * kD + j;
            float u0 = up[0], u1 = up[kD], u2 = up[2 * kD], u3 = up[3 * kD];
            float* ms = m0 + ptr * 2400 + j;
            float o0 = ms[0], o1 = ms[kMemRow], o2 = ms[2 * kMemRow], o3 = ms[3 * kMemRow];

            ull a0x = 0, a0y = 0, a1x = 0, a1y = 0, a2x = 0, a2y = 0, a3x = 0, a3y = 0;
            const ulonglong2* wp  = (const ulonglong2*)(Ws + j * KS);
            const ulonglong2* r0p = (const ulonglong2*)(ra);
            const ulonglong2* r1p = (const ulonglong2*)(ra + kD);
            const ulonglong2* r2p = (const ulonglong2*)(ra + 2 * kD);
            const ulonglong2* r3p = (const ulonglong2*)(ra + 3 * kD);
#pragma unroll
            for (int q = 0; q < KS / 4; q++) {
                ulonglong2 w = wp[q];
                ulonglong2 q0 = r0p[q], q1 = r1p[q], q2 = r2p[q], q3 = r3p[q];
                ffma2(a0x, q0.x, w.x, a0x); ffma2(a0y, q0.y, w.y, a0y);
                ffma2(a1x, q1.x, w.x, a1x); ffma2(a1y, q1.y, w.y, a1y);
                ffma2(a2x, q2.x, w.x, a2x); ffma2(a2y, q2.y, w.y, a2y);
                ffma2(a3x, q3.x, w.x, a3x); ffma2(a3y, q3.y, w.y, a3y);
            }
#pragma unroll
            for (int q = 0; q < KT / 4; q++) {
                ulonglong2 w = wr[q];
                ulonglong2 q0 = r0p[KS / 4 + q], q1 = r1p[KS / 4 + q];
                ulonglong2 q2 = r2p[KS / 4 + q], q3 = r3p[KS / 4 + q];
                ffma2(a0x, q0.x, w.x, a0x); ffma2(a0y, q0.y, w.y, a0y);
                ffma2(a1x, q1.x, w.x, a1x); ffma2(a1y, q1.y, w.y, a1y);
                ffma2(a2x, q2.x, w.x, a2x); ffma2(a2y, q2.y, w.y, a2y);
                ffma2(a3x, q3.x, w.x, a3x); ffma2(a3y, q3.y, w.y, a3y);
            }
            float h0 = tanhf(u0 + (pairsum(a0x) + pairsum(a0y)) * inv13);
            float h1 = tanhf(u1 + (pairsum(a1x) + pairsum(a1y)) * inv13);
            float h2 = tanhf(u2 + (pairsum(a2x) + pairsum(a2y)) * inv13);
            float h3 = tanhf(u3 + (pairsum(a3x) + pairsum(a3y)) * inv13);
            ms[0]           = h0;
            ms[kMemRow]     = h1;
            ms[2 * kMemRow] = h2;
            ms[3 * kMemRow] = h3;
            rb[j]          = ra[j]          + (h0 - o0);
            rb[kD + j]     = ra[kD + j]     + (h1 - o1);
            rb[2 * kD + j] = ra[2 * kD + j] + (h2 - o2);
            rb[3 * kD + j] = ra[3 * kD + j] + (h3 - o3);
        }
        __syncthreads();
        float* tmp = ra; ra = rb; rb = tmp;
    }
}

__global__ void x0_kernel(const float* __restrict__ we, const float* __restrict__ in_W,
                          const float* __restrict__ in_b) {
    int idx = blockIdx.x * blockDim.x + threadIdx.x;
    if (idx >= kB * kD) return;
    int b = idx / kD, j = idx % kD;
    const float* wr = we + (size_t)b * kL * kDin;
    float s = in_b[j];
    for (int d = 0; d < kDin; d++) s += wr[d] * in_W[d * kD + j];
    g_x0[idx] = s;
}

__global__ void skip_kernel(const float* __restrict__ skip_W, const float* __restrict__ skip_b) {
    int idx = blockIdx.x * blockDim.x + threadIdx.x;
    if (idx >= kB * kDin) return;
    int b = idx / kDin, i = idx % kDin;
    const float* x = g_x0 + (size_t)b * kD;
    float s = skip_b[i];
    for (int jj = 0; jj < kD; jj++) s += x[jj] * skip_W[jj * kDin + i];
    g_skip[idx] = s;
}

// cpre = mem_layer0 @ out_W(layer0 rows). 64 CTAs x 8 rows, 384 threads, FFMA2.
__global__ void outgemm_kernel(const float* __restrict__ mem, const float* __restrict__ outW) {
    extern __shared__ float X[];  // [8][3900]
    int b0 = blockIdx.x * 8, tid = threadIdx.x;
    for (int idx = tid; idx < 8 * 3900; idx += 384) {
        int r = idx / 3900, k = idx % 3900;
        int s = k / 300, d = k % 300;
        X[idx] = mem[(size_t)(b0 + r) * kMemRow + s * 2400 + d];
    }
    __syncthreads();
    int i = tid;
    ull accx[8], accy[8];
#pragma unroll
    for (int r = 0; r < 8; r++) { accx[r] = 0ull; accy[r] = 0ull; }
    for (int s = 0; s < 13; s++) {
        const float* wb = outW + (size_t)s * 2400 * kDin + i;
        const float* Xs = X + s * 300;
        for (int d4 = 0; d4 < 75; d4++) {
            float w0 = wb[(size_t)(d4 * 4 + 0) * kDin];
            float w1 = wb[(size_t)(d4 * 4 + 1) * kDin];
            float w2 = wb[(size_t)(d4 * 4 + 2) * kDin];
            float w3 = wb[(size_t)(d4 * 4 + 3) * kDin];
            ull w01 = packf2(w0, w1), w23 = packf2(w2, w3);
#pragma unroll
            for (int r = 0; r < 8; r++) {
                ulonglong2 x = *(const ulonglong2*)&Xs[r * 3900 + d4 * 4];
                ffma2(accx[r], x.x, w01, accx[r]);
                ffma2(accy[r], x.y, w23, accy[r]);
            }
        }
    }
#pragma unroll
    for (int r = 0; r < 8; r++)
        g_cpre[(size_t)(b0 + r) * kDin + i] = pairsum(accx[r]) + pairsum(accy[r]);
}

__global__ void final_kernel(const float* __restrict__ out_b,
                             const float* __restrict__ ln_g, const float* __restrict__ ln_b,
                             const float* __restrict__ W1, const float* __restrict__ b1,
                             const float* __restrict__ W2, const float* __restrict__ b2,
                             float* __restrict__ out) {
    __shared__ float cv[kDin];
    __shared__ float red[16];
    __shared__ float hid[64];
    int b = blockIdx.x, tid = threadIdx.x;
    int lane = tid & 31, wid = tid >> 5;

    float v = g_cpre[(size_t)b * kDin + tid] + out_b[tid] + g_skip[(size_t)b * kDin + tid];

    float s = v;
#pragma unroll
    for (int o = 16; o > 0; o >>= 1) s += __shfl_xor_sync(0xffffffffu, s, o);
    if (lane == 0) red[wid] = s;
    __syncthreads();
    if (tid == 0) {
        float t = 0.f;
        for (int w = 0; w < 12; w++) t += red[w];
        red[12] = t / kDin;
    }
    __syncthreads();
    float mu = red[12];
    float dv = v - mu;
    float s2 = dv * dv;
#pragma unroll
    for (int o = 16; o > 0; o >>= 1) s2 += __shfl_xor_sync(0xffffffffu, s2, o);
    if (lane == 0) red[wid] = s2;
    __syncthreads();
    if (tid == 0) {
        float t = 0.f;
        for (int w = 0; w < 12; w++) t += red[w];
        red[13] = rsqrtf(t / kDin + 1e-5f);
    }
    __syncthreads();
    float c = dv * red[13] * ln_g[tid] + ln_b[tid];
    out[(size_t)b * kDin + tid] = c;
    cv[tid] = c;
    __syncthreads();

    if (tid < 64) {
        float a = b1[tid];
        for (int d = 0; d < kDin; d++) a += cv[d] * W1[(size_t)d * 64 + tid];
        hid[tid] = fmaxf(a, 0.f) * W2[tid];
    }
    __syncthreads();
    if (tid == 0) {
        float lg = b2[0];
        for (int h = 0; h < 64; h++) lg += hid[h];
        out[kLogitOff + b] = lg;
    }
}

extern "C" void kernel_launch(void* const* d_in, const int* in_sizes, int n_in,
                              void* d_out, int out_size) {
    const float* we     = (const float*)d_in[0];
    const float* in_W   = (const float*)d_in[1];
    const float* in_b   = (const float*)d_in[2];
    const float* Wh     = (const float*)d_in[3];
    const float* Wr     = (const float*)d_in[4];
    const float* lb     = (const float*)d_in[5];
    const float* skip_W = (const float*)d_in[6];
    const float* skip_b = (const float*)d_in[7];
    const float* out_W  = (const float*)d_in[8];
    const float* out_b  = (const float*)d_in[9];
    const float* ln_g   = (const float*)d_in[10];
    const float* ln_b   = (const float*)d_in[11];
    const float* sh_W1  = (const float*)d_in[12];
    const float* sh_b1  = (const float*)d_in[13];
    const float* sh_W2  = (const float*)d_in[14];
    const float* sh_b2  = (const float*)d_in[15];
    float* out = (float*)d_out;

    cudaFuncSetAttribute(recur_kernel, cudaFuncAttributeMaxDynamicSharedMemorySize, RECUR_SMEM);
    cudaFuncSetAttribute(outgemm_kernel, cudaFuncAttributeMaxDynamicSharedMemorySize, OUTG_SMEM);

    cudaMemsetAsync(out + kMemOff, 0, (size_t)kB * kMemRow * sizeof(float));

    {
        int total = kDin * kD + kD * kD + kD;
        prep_kernel<<<(total + 255) / 256, 256>>>(in_W, in_b, Wh, Wr, lb);
    }
    // independent small kernels first (also shifts gemm_u onto the ncu -s 5 slot)
    x0_kernel<<<(kB * kD + 255) / 256, 256>>>(we, in_W, in_b);
    skip_kernel<<<(kB * kDin + 255) / 256, 256>>>(skip_W, skip_b);

    {
        dim3 grid((kD + 63) / 64, (kB * kL) / 128);
        gemm_u_kernel<<<grid, 256>>>(we);
    }

    recur_kernel<<<kB / 4, 320, RECUR_SMEM>>>(out + kMemOff);

    outgemm_kernel<<<kB / 8, 384, OUTG_SMEM>>>(out + kMemOff, out_W);

    final_kernel<<<kB, kDin>>>(out_b, ln_g, ln_b, sh_W1, sh_b1, sh_W2, sh_b2, out);
}